// round 16
// baseline (speedup 1.0000x reference)
#include <cuda_runtime.h>
#include <cuda_bf16.h>
#include <cuda_fp16.h>
#include <cstdint>

#define IN_DIM  256
#define OUT_DIM 128
#define MAX_NODES 50048
#define MAX_EDGES 800000
#define ROW_CAP 64                    // slots per row; P(deg>64)~1e-19 (Poisson 16)

#define BKT 32                        // K per SMEM tile
#define KTILES (IN_DIM / BKT)         // 8
#define BKP 40                        // padded fp16 row (elems) -> 80B rows

#define TILE_B   (128 * BKP * 2)      // 10240 B per padded fp16 tile
#define AF32_ROW 36                   // padded fp32 row (floats) -> 144B
#define AF32_B   (128 * AF32_ROW * 4) // 18432 B per fp32 A stage buffer

#define WF_OFF   (2 * AF32_B)
#define SAH_OFF  (WF_OFF + 2 * TILE_B)
#define GSMEM_BYTES (SAH_OFF + TILE_B)   // 67584

// ---------------------------------------------------------------------------
// Device scratch (no allocs allowed). g_count is zero at module load (BSS)
// and is RE-ZEROED by spmm_row_kernel at the end of every invocation, so no
// explicit zeroing kernel is needed (self-cleaning across graph replays).
// ---------------------------------------------------------------------------
__device__ __half g_support[MAX_NODES * OUT_DIM];    // X @ W in fp16
__device__ int    g_count[MAX_NODES];                // per-row edge count
__device__ int2   g_eslot[MAX_NODES * ROW_CAP];      // slotted CSR: (col, val-bits)
__device__ __half g_Wf[KTILES * 128 * BKT];          // W^T fp16 tiles [kt][n][k]

// ---------------------------------------------------------------------------
// PTX helpers (baseline ISA only)
// ---------------------------------------------------------------------------
__device__ __forceinline__ uint32_t smem_u32(const void* p) {
    uint32_t a;
    asm("{ .reg .u64 t; cvta.to.shared.u64 t, %1; cvt.u32.u64 %0, t; }" : "=r"(a) : "l"(p));
    return a;
}
__device__ __forceinline__ void ldsm_x4(uint32_t& r0, uint32_t& r1, uint32_t& r2, uint32_t& r3,
                                        uint32_t addr) {
    asm volatile("ldmatrix.sync.aligned.m8n8.x4.shared.b16 {%0,%1,%2,%3}, [%4];"
                 : "=r"(r0), "=r"(r1), "=r"(r2), "=r"(r3) : "r"(addr));
}
__device__ __forceinline__ void mma_f16(float* c, const uint32_t* a, uint32_t b0, uint32_t b1) {
    asm volatile(
        "mma.sync.aligned.m16n8k16.row.col.f32.f16.f16.f32 "
        "{%0,%1,%2,%3}, {%4,%5,%6,%7}, {%8,%9}, {%0,%1,%2,%3};"
        : "+f"(c[0]), "+f"(c[1]), "+f"(c[2]), "+f"(c[3])
        : "r"(a[0]), "r"(a[1]), "r"(a[2]), "r"(a[3]), "r"(b0), "r"(b1));
}
__device__ __forceinline__ void cp_async16(uint32_t dst, const void* src, int src_sz) {
    asm volatile("cp.async.cg.shared.global [%0], [%1], 16, %2;"
                 :: "r"(dst), "l"(src), "r"(src_sz) : "memory");
}

// ---------------------------------------------------------------------------
// Prep W: W[256,128] fp32 -> W^T fp16 tiles [kt][n][k]
// ---------------------------------------------------------------------------
__global__ void prep_w_kernel(const float* __restrict__ W)
{
    int i = blockIdx.x * blockDim.x + threadIdx.x;
    if (i >= IN_DIM * OUT_DIM) return;
    int k = i >> 7;
    int n = i & 127;
    int kt = k >> 5;
    int kk = k & 31;
    g_Wf[kt * (128 * BKT) + n * BKT + kk] = __float2half_rn(W[i]);
}

// ---------------------------------------------------------------------------
// GEMM: S[N,128] = X @ W via plain fp16 mma.sync (fp32 accumulate).
// ---------------------------------------------------------------------------
__global__ __launch_bounds__(256, 2)
void gemm_mma_kernel(const float* __restrict__ X, int N)
{
    extern __shared__ char dsm[];
    const uint32_t sbase = smem_u32(dsm);
    const uint32_t sah   = sbase + SAH_OFF;

    const int tid  = threadIdx.x;
    const int wid  = tid >> 5;
    const int lane = tid & 31;
    const int warp_m = wid & 3;
    const int warp_n = wid >> 2;
    const int block_row = blockIdx.x * 128;

    uint32_t a_off[2];
    #pragma unroll
    for (int mf = 0; mf < 2; mf++)
        a_off[mf] = (uint32_t)((warp_m * 32 + mf * 16 + (lane & 15)) * (BKP * 2) + (lane >> 4) * 16);
    uint32_t b_off[4];
    #pragma unroll
    for (int ng = 0; ng < 4; ng++)
        b_off[ng] = (uint32_t)((warp_n * 64 + ng * 16 + ((lane >> 4) & 1) * 8 + (lane & 7)) * (BKP * 2)
                               + ((lane >> 3) & 1) * 16);

    float acc[2][8][4];
    #pragma unroll
    for (int i = 0; i < 2; i++)
        #pragma unroll
        for (int j = 0; j < 8; j++)
            #pragma unroll
            for (int q = 0; q < 4; q++)
                acc[i][j][q] = 0.0f;

    int a_row[4], a_q[4], a_sz[4];
    const float* a_src[4];
    uint32_t a_dst[4];
    #pragma unroll
    for (int c = 0; c < 4; c++) {
        int chunk = tid + c * 256;
        a_row[c] = chunk >> 3;
        a_q[c]   = chunk & 7;
        int grow = block_row + a_row[c];
        a_sz[c]  = (grow < N) ? 16 : 0;
        int srow = (grow < N) ? grow : 0;
        a_src[c] = &X[(size_t)srow * IN_DIM + a_q[c] * 4];
        a_dst[c] = (uint32_t)(a_row[c] * (AF32_ROW * 4) + a_q[c] * 16);
    }
    int w_row[2], w_q[2];
    uint32_t w_dst[2];
    #pragma unroll
    for (int c = 0; c < 2; c++) {
        int chunk = tid + c * 256;
        w_row[c] = chunk >> 2;
        w_q[c]   = chunk & 3;
        w_dst[c] = (uint32_t)(w_row[c] * (BKP * 2) + w_q[c] * 16);
    }

    auto prefetch = [&](int kt, int buf) {
        uint32_t af = sbase + (uint32_t)buf * AF32_B;
        uint32_t wf = sbase + WF_OFF + (uint32_t)buf * TILE_B;
        #pragma unroll
        for (int c = 0; c < 4; c++)
            cp_async16(af + a_dst[c], a_src[c] + kt * BKT, a_sz[c]);
        #pragma unroll
        for (int c = 0; c < 2; c++) {
            const __half* ws = &g_Wf[kt * (128 * BKT) + w_row[c] * BKT + w_q[c] * 8];
            cp_async16(wf + w_dst[c], ws, 16);
        }
        asm volatile("cp.async.commit_group;" ::: "memory");
    };

    prefetch(0, 0);

    const int cv_row = tid >> 1;
    const int cv_h   = (tid & 1) * 16;

    #pragma unroll 1
    for (int kt = 0; kt < KTILES; kt++) {
        const int buf = kt & 1;
        if (kt + 1 < KTILES) {
            prefetch(kt + 1, buf ^ 1);
            asm volatile("cp.async.wait_group 1;" ::: "memory");
        } else {
            asm volatile("cp.async.wait_group 0;" ::: "memory");
        }
        __syncthreads();

        // Convert fp32 A stage -> fp16 padded tile
        {
            const float* af = reinterpret_cast<const float*>(
                dsm + buf * AF32_B) + cv_row * AF32_ROW + cv_h;
            char* dh = dsm + SAH_OFF + cv_row * (BKP * 2) + cv_h * 2;
            #pragma unroll
            for (int j = 0; j < 4; j++) {
                float4 v = *reinterpret_cast<const float4*>(af + j * 4);
                __half2 h0 = __floats2half2_rn(v.x, v.y);
                __half2 h1 = __floats2half2_rn(v.z, v.w);
                *reinterpret_cast<uint2*>(dh + j * 8) =
                    make_uint2(*reinterpret_cast<uint32_t*>(&h0),
                               *reinterpret_cast<uint32_t*>(&h1));
            }
        }
        __syncthreads();

        const uint32_t bwf = sbase + WF_OFF + (uint32_t)buf * TILE_B;

        #pragma unroll
        for (int ks = 0; ks < 2; ks++) {
            const uint32_t kb = (uint32_t)(ks * 32);

            uint32_t ah[2][4];
            #pragma unroll
            for (int mf = 0; mf < 2; mf++)
                ldsm_x4(ah[mf][0], ah[mf][1], ah[mf][2], ah[mf][3], sah + a_off[mf] + kb);
            uint32_t bh[8][2];
            #pragma unroll
            for (int ng = 0; ng < 4; ng++) {
                uint32_t r0, r1, r2, r3;
                ldsm_x4(r0, r1, r2, r3, bwf + b_off[ng] + kb);
                bh[ng * 2][0] = r0; bh[ng * 2][1] = r1;
                bh[ng * 2 + 1][0] = r2; bh[ng * 2 + 1][1] = r3;
            }
            #pragma unroll
            for (int mf = 0; mf < 2; mf++)
                #pragma unroll
                for (int nf = 0; nf < 8; nf++)
                    mma_f16(acc[mf][nf], ah[mf], bh[nf][0], bh[nf][1]);
        }
        __syncthreads();
    }

    const int r_base = block_row + warp_m * 32 + (lane >> 2);
    const int c_base = warp_n * 64 + (lane & 3) * 2;
    #pragma unroll
    for (int mf = 0; mf < 2; mf++) {
        int r0 = r_base + mf * 16;
        int r1 = r0 + 8;
        #pragma unroll
        for (int nf = 0; nf < 8; nf++) {
            int c = c_base + nf * 8;
            if (r0 < N)
                *reinterpret_cast<__half2*>(&g_support[(size_t)r0 * OUT_DIM + c]) =
                    __floats2half2_rn(acc[mf][nf][0], acc[mf][nf][1]);
            if (r1 < N)
                *reinterpret_cast<__half2*>(&g_support[(size_t)r1 * OUT_DIM + c]) =
                    __floats2half2_rn(acc[mf][nf][2], acc[mf][nf][3]);
        }
    }
}

// ---------------------------------------------------------------------------
// Slotted CSR build: direct scatter. Counts are zero on entry (BSS init on
// first call; reset by spmm_row_kernel on every call thereafter).
// ---------------------------------------------------------------------------
__global__ void scatter_direct_kernel(const int* __restrict__ rows,
                                      const int* __restrict__ cols,
                                      const float* __restrict__ vals, int E)
{
    int i = blockIdx.x * blockDim.x + threadIdx.x;
    if (i < E) {
        int r = rows[i];
        int p = atomicAdd(&g_count[r], 1);
        if (p < ROW_CAP)   // statistically never taken; memory-safety guard
            g_eslot[(size_t)r * ROW_CAP + p] = make_int2(cols[i], __float_as_int(vals[i]));
    }
}

// ---------------------------------------------------------------------------
// SpMM: row-parallel over fp16 support. One warp per row; fp32 accumulate.
// Reads the slotted CSR, then resets g_count[row]=0 for the next invocation.
// ---------------------------------------------------------------------------
__global__ __launch_bounds__(256)
void spmm_row_kernel(const float* __restrict__ bias, float* __restrict__ out, int N)
{
    int row  = (blockIdx.x * blockDim.x + threadIdx.x) >> 5;
    int lane = threadIdx.x & 31;
    if (row >= N) return;

    int cnt = g_count[row];
    if (lane == 0) g_count[row] = 0;     // self-clean for next replay
    if (cnt > ROW_CAP) cnt = ROW_CAP;
    const int2* ep = &g_eslot[(size_t)row * ROW_CAP];

    float4 acc  = *reinterpret_cast<const float4*>(&bias[lane * 4]);
    float4 acc2 = make_float4(0.f, 0.f, 0.f, 0.f);

    int i = 0;
    for (; i + 1 < cnt; i += 2) {
        int2 p0 = __ldg(&ep[i]);
        int2 p1 = __ldg(&ep[i + 1]);
        float v0 = __int_as_float(p0.y);
        float v1 = __int_as_float(p1.y);
        uint2 u0 = *reinterpret_cast<const uint2*>(&g_support[(size_t)p0.x * OUT_DIM + lane * 4]);
        uint2 u1 = *reinterpret_cast<const uint2*>(&g_support[(size_t)p1.x * OUT_DIM + lane * 4]);
        float2 f0a = __half22float2(*reinterpret_cast<__half2*>(&u0.x));
        float2 f0b = __half22float2(*reinterpret_cast<__half2*>(&u0.y));
        float2 f1a = __half22float2(*reinterpret_cast<__half2*>(&u1.x));
        float2 f1b = __half22float2(*reinterpret_cast<__half2*>(&u1.y));
        acc.x  = fmaf(v0, f0a.x, acc.x);  acc.y  = fmaf(v0, f0a.y, acc.y);
        acc.z  = fmaf(v0, f0b.x, acc.z);  acc.w  = fmaf(v0, f0b.y, acc.w);
        acc2.x = fmaf(v1, f1a.x, acc2.x); acc2.y = fmaf(v1, f1a.y, acc2.y);
        acc2.z = fmaf(v1, f1b.x, acc2.z); acc2.w = fmaf(v1, f1b.y, acc2.w);
    }
    if (i < cnt) {
        int2 p = __ldg(&ep[i]);
        float v = __int_as_float(p.y);
        uint2 u = *reinterpret_cast<const uint2*>(&g_support[(size_t)p.x * OUT_DIM + lane * 4]);
        float2 fa = __half22float2(*reinterpret_cast<__half2*>(&u.x));
        float2 fb = __half22float2(*reinterpret_cast<__half2*>(&u.y));
        acc.x = fmaf(v, fa.x, acc.x); acc.y = fmaf(v, fa.y, acc.y);
        acc.z = fmaf(v, fb.x, acc.z); acc.w = fmaf(v, fb.y, acc.w);
    }
    acc.x += acc2.x; acc.y += acc2.y; acc.z += acc2.z; acc.w += acc2.w;

    *reinterpret_cast<float4*>(&out[(size_t)row * OUT_DIM + lane * 4]) = acc;
}

// ---------------------------------------------------------------------------
// Launch: two-stream fork/join (dense path || scatter), join -> SpMM.
// inputs: 0=adj_rows[E] i32, 1=adj_cols[E] i32, 2=adj_vals[E] f32,
//         3=x[N,256] f32, 4=W[256,128] f32, 5=b[128] f32
// ---------------------------------------------------------------------------
extern "C" void kernel_launch(void* const* d_in, const int* in_sizes, int n_in,
                              void* d_out, int out_size)
{
    const int*   rows = (const int*)  d_in[0];
    const int*   cols = (const int*)  d_in[1];
    const float* vals = (const float*)d_in[2];
    const float* x    = (const float*)d_in[3];
    const float* W    = (const float*)d_in[4];
    const float* b    = (const float*)d_in[5];
    float* out = (float*)d_out;

    const int E = in_sizes[0];
    const int N = in_sizes[3] / IN_DIM;

    cudaFuncSetAttribute(gemm_mma_kernel,
                         cudaFuncAttributeMaxDynamicSharedMemorySize, GSMEM_BYTES);

    cudaStream_t s2;
    cudaStreamCreateWithFlags(&s2, cudaStreamNonBlocking);
    cudaEvent_t ev_fork, ev_join;
    cudaEventCreateWithFlags(&ev_fork, cudaEventDisableTiming);
    cudaEventCreateWithFlags(&ev_join, cudaEventDisableTiming);

    cudaEventRecord(ev_fork, 0);
    cudaStreamWaitEvent(s2, ev_fork, 0);

    // --- Main stream: dense path ---
    prep_w_kernel<<<(IN_DIM * OUT_DIM + 255) / 256, 256>>>(W);
    gemm_mma_kernel<<<(N + 127) / 128, 256, GSMEM_BYTES>>>(x, N);

    // --- Side stream: slotted CSR scatter (counts pre-zeroed) ---
    scatter_direct_kernel<<<(E + 255) / 256, 256, 0, s2>>>(rows, cols, vals, E);

    cudaEventRecord(ev_join, s2);
    cudaStreamWaitEvent(0, ev_join, 0);

    // Sparse: out = A @ support + b  (also resets g_count for next call)
    spmm_row_kernel<<<(N * 32 + 255) / 256, 256>>>(b, out, N);

    cudaEventDestroy(ev_fork);
    cudaEventDestroy(ev_join);
    cudaStreamDestroy(s2);
}

// round 17
// speedup vs baseline: 1.5888x; 1.5888x over previous
#include <cuda_runtime.h>
#include <cuda_bf16.h>
#include <cuda_fp16.h>
#include <cstdint>

#define IN_DIM  256
#define OUT_DIM 128
#define MAX_NODES 50048
#define MAX_EDGES 800000
#define ROW_CAP 64                    // slots per row; P(deg>64)~1e-19 (Poisson 16)

#define BKT 32                        // K per SMEM tile
#define KTILES (IN_DIM / BKT)         // 8
#define BKP 40                        // padded fp16 row (elems) -> 80B rows

#define TILE_B    (128 * BKP * 2)     // 10240 B per padded fp16 tile
#define AF32_ROW  36                  // padded fp32 A row (floats) -> 144B
#define AF32_B    (128 * AF32_ROW * 4)// 18432 B per fp32 A stage buffer
#define WF32_ROW  132                 // padded fp32 W row (floats) -> 528B
#define WF32_B    (32 * WF32_ROW * 4) // 16896 B per fp32 W stage buffer

// Dynamic SMEM layout:
//   [0)        A f32 stage buf0/buf1  (2 x 18432)
//   [WS_OFF)   W f32 stage buf0/buf1  (2 x 16896)
//   [SAH_OFF)  converted A fp16 tile  (10240)
//   [SWH_OFF)  converted W fp16 tile  (10240)
#define WS_OFF   (2 * AF32_B)                 // 36864
#define SAH_OFF  (WS_OFF + 2 * WF32_B)        // 70656
#define SWH_OFF  (SAH_OFF + TILE_B)           // 80896
#define GSMEM_BYTES (SWH_OFF + TILE_B)        // 91136  (2 CTAs/SM: 182272 <= 228K)

// ---------------------------------------------------------------------------
// Device scratch (no allocs allowed)
// ---------------------------------------------------------------------------
__device__ __half g_support[MAX_NODES * OUT_DIM];    // X @ W in fp16
__device__ int    g_count[MAX_NODES];                // per-row edge count
__device__ int2   g_eslot[MAX_NODES * ROW_CAP];      // slotted CSR: (col, val-bits)

// ---------------------------------------------------------------------------
// PTX helpers (baseline ISA only)
// ---------------------------------------------------------------------------
__device__ __forceinline__ uint32_t smem_u32(const void* p) {
    uint32_t a;
    asm("{ .reg .u64 t; cvta.to.shared.u64 t, %1; cvt.u32.u64 %0, t; }" : "=r"(a) : "l"(p));
    return a;
}
__device__ __forceinline__ void ldsm_x4(uint32_t& r0, uint32_t& r1, uint32_t& r2, uint32_t& r3,
                                        uint32_t addr) {
    asm volatile("ldmatrix.sync.aligned.m8n8.x4.shared.b16 {%0,%1,%2,%3}, [%4];"
                 : "=r"(r0), "=r"(r1), "=r"(r2), "=r"(r3) : "r"(addr));
}
__device__ __forceinline__ void mma_f16(float* c, const uint32_t* a, uint32_t b0, uint32_t b1) {
    asm volatile(
        "mma.sync.aligned.m16n8k16.row.col.f32.f16.f16.f32 "
        "{%0,%1,%2,%3}, {%4,%5,%6,%7}, {%8,%9}, {%0,%1,%2,%3};"
        : "+f"(c[0]), "+f"(c[1]), "+f"(c[2]), "+f"(c[3])
        : "r"(a[0]), "r"(a[1]), "r"(a[2]), "r"(a[3]), "r"(b0), "r"(b1));
}
__device__ __forceinline__ void cp_async16(uint32_t dst, const void* src, int src_sz) {
    asm volatile("cp.async.cg.shared.global [%0], [%1], 16, %2;"
                 :: "r"(dst), "l"(src), "r"(src_sz) : "memory");
}

// ---------------------------------------------------------------------------
// GEMM: S[N,128] = X @ W via plain fp16 mma.sync (fp32 accumulate).
// Both A (X) and B (W) staged as fp32 via cp.async (double-buffered) and
// converted to fp16 in SMEM. W conversion also transposes [k][n] -> [n][k].
// CTA 128x128, 256 threads = 8 warps (4M x 2N). fp16 output. No prep kernel.
// ---------------------------------------------------------------------------
__global__ __launch_bounds__(256, 2)
void gemm_mma_kernel(const float* __restrict__ X, const float* __restrict__ W, int N)
{
    extern __shared__ char dsm[];
    const uint32_t sbase = smem_u32(dsm);
    const uint32_t sah   = sbase + SAH_OFF;
    const uint32_t swh   = sbase + SWH_OFF;

    const int tid  = threadIdx.x;
    const int wid  = tid >> 5;
    const int lane = tid & 31;
    const int warp_m = wid & 3;
    const int warp_n = wid >> 2;
    const int block_row = blockIdx.x * 128;

    // ldmatrix offsets (within padded fp16 tiles)
    uint32_t a_off[2];
    #pragma unroll
    for (int mf = 0; mf < 2; mf++)
        a_off[mf] = (uint32_t)((warp_m * 32 + mf * 16 + (lane & 15)) * (BKP * 2) + (lane >> 4) * 16);
    uint32_t b_off[4];
    #pragma unroll
    for (int ng = 0; ng < 4; ng++)
        b_off[ng] = (uint32_t)((warp_n * 64 + ng * 16 + ((lane >> 4) & 1) * 8 + (lane & 7)) * (BKP * 2)
                               + ((lane >> 3) & 1) * 16);

    float acc[2][8][4];
    #pragma unroll
    for (int i = 0; i < 2; i++)
        #pragma unroll
        for (int j = 0; j < 8; j++)
            #pragma unroll
            for (int q = 0; q < 4; q++)
                acc[i][j][q] = 0.0f;

    // --- cp.async assignments ---
    // A fp32 tile: 128 rows x 8 chunks(16B) = 1024 chunks, 4 per thread.
    int a_sz[4];
    const float* a_src[4];
    uint32_t a_dst[4];
    #pragma unroll
    for (int c = 0; c < 4; c++) {
        int chunk = tid + c * 256;
        int r  = chunk >> 3;
        int q  = chunk & 7;
        int grow = block_row + r;
        a_sz[c]  = (grow < N) ? 16 : 0;
        int srow = (grow < N) ? grow : 0;
        a_src[c] = &X[(size_t)srow * IN_DIM + q * 4];
        a_dst[c] = (uint32_t)(r * (AF32_ROW * 4) + q * 16);
    }
    // W fp32 tile: 32 k-rows x 32 chunks(16B; 128 floats/row) = 1024 chunks, 4/thread.
    const float* w_src[4];
    uint32_t w_dst[4];
    #pragma unroll
    for (int c = 0; c < 4; c++) {
        int chunk = tid + c * 256;
        int kr = chunk >> 5;          // 0..31
        int q  = chunk & 31;          // 16B units within 512B row
        w_src[c] = &W[(size_t)kr * OUT_DIM + q * 4];
        w_dst[c] = (uint32_t)(kr * (WF32_ROW * 4) + q * 16);
    }

    auto prefetch = [&](int kt, int buf) {
        uint32_t af = sbase + (uint32_t)buf * AF32_B;
        uint32_t wf = sbase + WS_OFF + (uint32_t)buf * WF32_B;
        #pragma unroll
        for (int c = 0; c < 4; c++)
            cp_async16(af + a_dst[c], a_src[c] + kt * BKT, a_sz[c]);
        #pragma unroll
        for (int c = 0; c < 4; c++)
            cp_async16(wf + w_dst[c], w_src[c] + (size_t)kt * BKT * OUT_DIM, 16);
        asm volatile("cp.async.commit_group;" ::: "memory");
    };

    prefetch(0, 0);

    // Convert assignment: thread -> row tid>>1, half (tid&1)*16
    const int cv_row = tid >> 1;          // A: m-row / W: n-col (both 0..127)
    const int cv_h   = (tid & 1) * 16;    // k offset 0 or 16

    #pragma unroll 1
    for (int kt = 0; kt < KTILES; kt++) {
        const int buf = kt & 1;
        if (kt + 1 < KTILES) {
            prefetch(kt + 1, buf ^ 1);
            asm volatile("cp.async.wait_group 1;" ::: "memory");
        } else {
            asm volatile("cp.async.wait_group 0;" ::: "memory");
        }
        __syncthreads();

        // --- Convert fp32 A stage -> fp16 padded tile ---
        {
            const float* af = reinterpret_cast<const float*>(
                dsm + buf * AF32_B) + cv_row * AF32_ROW + cv_h;
            char* dh = dsm + SAH_OFF + cv_row * (BKP * 2) + cv_h * 2;
            #pragma unroll
            for (int j = 0; j < 4; j++) {
                float4 v = *reinterpret_cast<const float4*>(af + j * 4);
                __half2 h0 = __floats2half2_rn(v.x, v.y);
                __half2 h1 = __floats2half2_rn(v.z, v.w);
                *reinterpret_cast<uint2*>(dh + j * 8) =
                    make_uint2(*reinterpret_cast<uint32_t*>(&h0),
                               *reinterpret_cast<uint32_t*>(&h1));
            }
        }
        // --- Convert + transpose fp32 W stage [k][n] -> fp16 [n][k] tile ---
        {
            const float* wf = reinterpret_cast<const float*>(
                dsm + WS_OFF + buf * WF32_B) + cv_row;   // column cv_row (= n)
            __half hb[16];
            #pragma unroll
            for (int j = 0; j < 16; j++)
                hb[j] = __float2half_rn(wf[(size_t)(cv_h + j) * WF32_ROW]);
            char* dw = dsm + SWH_OFF + cv_row * (BKP * 2) + cv_h * 2;
            const uint4* hb4 = reinterpret_cast<const uint4*>(hb);
            *reinterpret_cast<uint4*>(dw)      = hb4[0];
            *reinterpret_cast<uint4*>(dw + 16) = hb4[1];
        }
        __syncthreads();

        #pragma unroll
        for (int ks = 0; ks < 2; ks++) {
            const uint32_t kb = (uint32_t)(ks * 32);

            uint32_t ah[2][4];
            #pragma unroll
            for (int mf = 0; mf < 2; mf++)
                ldsm_x4(ah[mf][0], ah[mf][1], ah[mf][2], ah[mf][3], sah + a_off[mf] + kb);
            uint32_t bh[8][2];
            #pragma unroll
            for (int ng = 0; ng < 4; ng++) {
                uint32_t r0, r1, r2, r3;
                ldsm_x4(r0, r1, r2, r3, swh + b_off[ng] + kb);
                bh[ng * 2][0] = r0; bh[ng * 2][1] = r1;
                bh[ng * 2 + 1][0] = r2; bh[ng * 2 + 1][1] = r3;
            }
            #pragma unroll
            for (int mf = 0; mf < 2; mf++)
                #pragma unroll
                for (int nf = 0; nf < 8; nf++)
                    mma_f16(acc[mf][nf], ah[mf], bh[nf][0], bh[nf][1]);
        }
        __syncthreads();
    }

    // Epilogue -> fp16 support
    const int r_base = block_row + warp_m * 32 + (lane >> 2);
    const int c_base = warp_n * 64 + (lane & 3) * 2;
    #pragma unroll
    for (int mf = 0; mf < 2; mf++) {
        int r0 = r_base + mf * 16;
        int r1 = r0 + 8;
        #pragma unroll
        for (int nf = 0; nf < 8; nf++) {
            int c = c_base + nf * 8;
            if (r0 < N)
                *reinterpret_cast<__half2*>(&g_support[(size_t)r0 * OUT_DIM + c]) =
                    __floats2half2_rn(acc[mf][nf][0], acc[mf][nf][1]);
            if (r1 < N)
                *reinterpret_cast<__half2*>(&g_support[(size_t)r1 * OUT_DIM + c]) =
                    __floats2half2_rn(acc[mf][nf][2], acc[mf][nf][3]);
        }
    }
}

// ---------------------------------------------------------------------------
// Slotted CSR build: zero counts -> direct scatter (no hist, no scan).
// ---------------------------------------------------------------------------
__global__ void zero_counts_kernel(int n4)
{
    int i = blockIdx.x * blockDim.x + threadIdx.x;
    if (i < n4) reinterpret_cast<int4*>(g_count)[i] = make_int4(0, 0, 0, 0);
}

__global__ void scatter_direct_kernel(const int* __restrict__ rows,
                                      const int* __restrict__ cols,
                                      const float* __restrict__ vals, int E)
{
    int i = blockIdx.x * blockDim.x + threadIdx.x;
    if (i < E) {
        int r = rows[i];
        int p = atomicAdd(&g_count[r], 1);
        if (p < ROW_CAP)   // statistically never taken; memory-safety guard
            g_eslot[(size_t)r * ROW_CAP + p] = make_int2(cols[i], __float_as_int(vals[i]));
    }
}

// ---------------------------------------------------------------------------
// SpMM: row-parallel over fp16 support. One warp per row; fp32 accumulate.
// Reads the slotted CSR at row*ROW_CAP. (Exact R14 form.)
// ---------------------------------------------------------------------------
__global__ __launch_bounds__(256)
void spmm_row_kernel(const float* __restrict__ bias, float* __restrict__ out, int N)
{
    int row  = (blockIdx.x * blockDim.x + threadIdx.x) >> 5;
    int lane = threadIdx.x & 31;
    if (row >= N) return;

    int cnt = g_count[row];
    if (cnt > ROW_CAP) cnt = ROW_CAP;
    const int2* ep = &g_eslot[(size_t)row * ROW_CAP];

    float4 acc  = *reinterpret_cast<const float4*>(&bias[lane * 4]);
    float4 acc2 = make_float4(0.f, 0.f, 0.f, 0.f);

    int i = 0;
    for (; i + 1 < cnt; i += 2) {
        int2 p0 = __ldg(&ep[i]);
        int2 p1 = __ldg(&ep[i + 1]);
        float v0 = __int_as_float(p0.y);
        float v1 = __int_as_float(p1.y);
        uint2 u0 = *reinterpret_cast<const uint2*>(&g_support[(size_t)p0.x * OUT_DIM + lane * 4]);
        uint2 u1 = *reinterpret_cast<const uint2*>(&g_support[(size_t)p1.x * OUT_DIM + lane * 4]);
        float2 f0a = __half22float2(*reinterpret_cast<__half2*>(&u0.x));
        float2 f0b = __half22float2(*reinterpret_cast<__half2*>(&u0.y));
        float2 f1a = __half22float2(*reinterpret_cast<__half2*>(&u1.x));
        float2 f1b = __half22float2(*reinterpret_cast<__half2*>(&u1.y));
        acc.x  = fmaf(v0, f0a.x, acc.x);  acc.y  = fmaf(v0, f0a.y, acc.y);
        acc.z  = fmaf(v0, f0b.x, acc.z);  acc.w  = fmaf(v0, f0b.y, acc.w);
        acc2.x = fmaf(v1, f1a.x, acc2.x); acc2.y = fmaf(v1, f1a.y, acc2.y);
        acc2.z = fmaf(v1, f1b.x, acc2.z); acc2.w = fmaf(v1, f1b.y, acc2.w);
    }
    if (i < cnt) {
        int2 p = __ldg(&ep[i]);
        float v = __int_as_float(p.y);
        uint2 u = *reinterpret_cast<const uint2*>(&g_support[(size_t)p.x * OUT_DIM + lane * 4]);
        float2 fa = __half22float2(*reinterpret_cast<__half2*>(&u.x));
        float2 fb = __half22float2(*reinterpret_cast<__half2*>(&u.y));
        acc.x = fmaf(v, fa.x, acc.x); acc.y = fmaf(v, fa.y, acc.y);
        acc.z = fmaf(v, fb.x, acc.z); acc.w = fmaf(v, fb.y, acc.w);
    }
    acc.x += acc2.x; acc.y += acc2.y; acc.z += acc2.z; acc.w += acc2.w;

    *reinterpret_cast<float4*>(&out[(size_t)row * OUT_DIM + lane * 4]) = acc;
}

// ---------------------------------------------------------------------------
// Launch: two-stream fork/join (GEMM || zero+scatter), join -> SpMM.
// inputs: 0=adj_rows[E] i32, 1=adj_cols[E] i32, 2=adj_vals[E] f32,
//         3=x[N,256] f32, 4=W[256,128] f32, 5=b[128] f32
// ---------------------------------------------------------------------------
extern "C" void kernel_launch(void* const* d_in, const int* in_sizes, int n_in,
                              void* d_out, int out_size)
{
    const int*   rows = (const int*)  d_in[0];
    const int*   cols = (const int*)  d_in[1];
    const float* vals = (const float*)d_in[2];
    const float* x    = (const float*)d_in[3];
    const float* W    = (const float*)d_in[4];
    const float* b    = (const float*)d_in[5];
    float* out = (float*)d_out;

    const int E = in_sizes[0];
    const int N = in_sizes[3] / IN_DIM;

    cudaFuncSetAttribute(gemm_mma_kernel,
                         cudaFuncAttributeMaxDynamicSharedMemorySize, GSMEM_BYTES);

    cudaStream_t s2;
    cudaStreamCreateWithFlags(&s2, cudaStreamNonBlocking);
    cudaEvent_t ev_fork, ev_join;
    cudaEventCreateWithFlags(&ev_fork, cudaEventDisableTiming);
    cudaEventCreateWithFlags(&ev_join, cudaEventDisableTiming);

    cudaEventRecord(ev_fork, 0);
    cudaStreamWaitEvent(s2, ev_fork, 0);

    // --- Main stream: dense path (single fused GEMM, no prep kernel) ---
    gemm_mma_kernel<<<(N + 127) / 128, 256, GSMEM_BYTES>>>(x, W, N);

    // --- Side stream: slotted CSR (zero -> direct scatter) ---
    int n4 = (N + 3) / 4;
    zero_counts_kernel<<<(n4 + 255) / 256, 256, 0, s2>>>(n4);
    scatter_direct_kernel<<<(E + 255) / 256, 256, 0, s2>>>(rows, cols, vals, E);

    cudaEventRecord(ev_join, s2);
    cudaStreamWaitEvent(0, ev_join, 0);

    // Sparse: out = A @ support + b
    spmm_row_kernel<<<(N * 32 + 255) / 256, 256>>>(b, out, N);

    cudaEventDestroy(ev_fork);
    cudaEventDestroy(ev_join);
    cudaStreamDestroy(s2);
}